// round 17
// baseline (speedup 1.0000x reference)
#include <cuda_runtime.h>
#include <cuda_fp16.h>
#include <cstdint>

// ============================================================================
// GCN layer: out = relu(diag(d) A diag(d) X W + b), d = rsqrt(rowsum(A))
// R16: no A_h pass. GEMM stages A via LDG(f32)->cvt->STS (one tile ahead),
//      B via cp.async. KT=32, RING=4, 2 CTAs/SM, ldsm frags, KSPLIT=4.
//   k1: d = rsqrt(rowsum A)            (pure 256MB read)
//   k2: Zt_h[n,k] = f16( d_k * (X@W)[k,n] )
//   k3: part[s] = f16(A) @ Zt_h^T      (HMMA m16n8k16)
//   k4: out = relu(d_m * sum_s p_s + b)
// ============================================================================

#define NROWS 8192
#define FDIM  128
#define ODIM  128
#define KSPLIT 4

__device__ __align__(128) float  g_d[NROWS];
__device__ __align__(128) __half g_Zth[ODIM * NROWS];                    // [n][k] f16
__device__ __align__(128) float  g_part[KSPLIT * (size_t)NROWS * ODIM];  // partials

// ---------------------------------------------------------------------------
__device__ __forceinline__ uint32_t smem_u32(const void* p) {
    uint32_t a;
    asm("{ .reg .u64 t; cvta.to.shared.u64 t, %1; cvt.u32.u64 %0, t; }"
        : "=r"(a) : "l"(p));
    return a;
}

#define CPA16(dst, src) \
    asm volatile("cp.async.cg.shared.global [%0], [%1], 16;" :: "r"(dst), "l"(src) : "memory")
#define CPA_COMMIT() asm volatile("cp.async.commit_group;" ::: "memory")
#define CPA_WAIT(n)  asm volatile("cp.async.wait_group %0;" :: "n"(n) : "memory")

__device__ __forceinline__ void mma_f16(float* c, const uint32_t* a,
                                        uint32_t b0, uint32_t b1) {
    asm volatile(
        "mma.sync.aligned.m16n8k16.row.col.f32.f16.f16.f32 "
        "{%0,%1,%2,%3}, {%4,%5,%6,%7}, {%8,%9}, {%0,%1,%2,%3};"
        : "+f"(c[0]), "+f"(c[1]), "+f"(c[2]), "+f"(c[3])
        : "r"(a[0]), "r"(a[1]), "r"(a[2]), "r"(a[3]), "r"(b0), "r"(b1));
}

__device__ __forceinline__ void ldsm_x4(uint32_t* d, uint32_t addr) {
    asm volatile("ldmatrix.sync.aligned.m8n8.x4.shared.b16 {%0,%1,%2,%3}, [%4];"
        : "=r"(d[0]), "=r"(d[1]), "=r"(d[2]), "=r"(d[3]) : "r"(addr));
}

// ---------------------------------------------------------------------------
// Kernel 1: d[r] = rsqrt(sum_k A[r,k])  (pure read, BW floor)
// ---------------------------------------------------------------------------
__global__ __launch_bounds__(256) void rowsum_kernel(const float* __restrict__ A) {
    int row = blockIdx.x;
    const float4* p = reinterpret_cast<const float4*>(A + (size_t)row * NROWS);
    float s = 0.f;
#pragma unroll
    for (int i = 0; i < 8; ++i) {
        float4 v = p[threadIdx.x + i * 256];
        s += (v.x + v.y) + (v.z + v.w);
    }
#pragma unroll
    for (int o = 16; o; o >>= 1) s += __shfl_xor_sync(0xffffffffu, s, o);
    __shared__ float ws[8];
    if ((threadIdx.x & 31) == 0) ws[threadIdx.x >> 5] = s;
    __syncthreads();
    if (threadIdx.x < 8) {
        float t = ws[threadIdx.x];
        t += __shfl_xor_sync(0xffu, t, 4);
        t += __shfl_xor_sync(0xffu, t, 2);
        t += __shfl_xor_sync(0xffu, t, 1);
        if (threadIdx.x == 0) g_d[row] = rsqrtf(t);
    }
}

// ---------------------------------------------------------------------------
// Kernel 2: Zt_h[n,k] = f16_rn( d[k] * sum_f X[k,f] W[f,n] )
// ---------------------------------------------------------------------------
__global__ __launch_bounds__(256) void xw_kernel(const float* __restrict__ X,
                                                 const float* __restrict__ W) {
    __shared__ float Ws[128 * 64];
    __shared__ float Xs[16 * 128];
    int tid = threadIdx.x;
    int n0 = blockIdx.y * 64;
    int k0 = blockIdx.x * 16;
    for (int i = tid; i < 128 * 64; i += 256) {
        int f = i >> 6, nl = i & 63;
        Ws[i] = W[f * ODIM + n0 + nl];
    }
    for (int i = tid; i < 16 * 128; i += 256)
        Xs[i] = X[(size_t)(k0 + (i >> 7)) * FDIM + (i & 127)];
    __syncthreads();

    int nl = tid & 63, ks = tid >> 6;
    for (int kk = ks; kk < 16; kk += 4) {
        float acc = 0.f;
#pragma unroll 8
        for (int f = 0; f < 128; ++f) acc += Xs[kk * 128 + f] * Ws[f * 64 + nl];
        int k = k0 + kk;
        g_Zth[(size_t)(n0 + nl) * NROWS + k] = __float2half_rn(g_d[k] * acc);
    }
}

// ---------------------------------------------------------------------------
// Kernel 3: GEMM. grid (64,4), 256 thr (8 warps, 64x32 warp tile).
// CTA 128x128, KT=32, RING=4, 2 CTAs/SM. A: LDG f32 -> cvt -> STS one tile
// ahead (f16 in smem, 80B rows). B: cp.async f16. ldsm.x4 fragments.
// ---------------------------------------------------------------------------
static constexpr int KT       = 32;
static constexpr int KC       = NROWS / KSPLIT;  // 2048 per K-split
static constexpr int NKT      = KC / KT;         // 64
static constexpr int ROW_B    = 80;              // 64B f16 payload + 16B pad
static constexpr int TILE_B   = 128 * ROW_B;     // 10240 B
static constexpr int RING     = 4;
static constexpr int DYN_SMEM = 2 * RING * TILE_B;  // 81920 -> 2 CTAs/SM

// A staging: thread -> row = tid>>1, half = tid&1 (16 f32 = 4 float4)
__device__ __forceinline__ void ldgA(const float* __restrict__ A, int m0,
                                     int kbase, int t, int tid, float4* R) {
    int row = tid >> 1, half = tid & 1;
    const float4* src = reinterpret_cast<const float4*>(
        A + (size_t)(m0 + row) * NROWS + kbase + t * KT + half * 16);
#pragma unroll
    for (int i = 0; i < 4; ++i) R[i] = src[i];
}

__device__ __forceinline__ void cvtSTS(uint32_t Ad, int tid, const float4* R) {
    int row = tid >> 1, half = tid & 1;
    uint32_t dst = Ad + (uint32_t)(row * ROW_B + half * 32);
#pragma unroll
    for (int i = 0; i < 2; ++i) {
        uint32_t u0, u1, u2, u3;
        asm("cvt.rn.f16x2.f32 %0, %1, %2;" : "=r"(u0) : "f"(R[2*i].y),   "f"(R[2*i].x));
        asm("cvt.rn.f16x2.f32 %0, %1, %2;" : "=r"(u1) : "f"(R[2*i].w),   "f"(R[2*i].z));
        asm("cvt.rn.f16x2.f32 %0, %1, %2;" : "=r"(u2) : "f"(R[2*i+1].y), "f"(R[2*i+1].x));
        asm("cvt.rn.f16x2.f32 %0, %1, %2;" : "=r"(u3) : "f"(R[2*i+1].w), "f"(R[2*i+1].z));
        asm volatile("st.shared.v4.b32 [%0], {%1,%2,%3,%4};"
                     :: "r"(dst + i * 16u), "r"(u0), "r"(u1), "r"(u2), "r"(u3)
                     : "memory");
    }
}

__device__ __forceinline__ void cpaB(uint32_t Bd, int kbase, int t, int tid) {
    int k0 = kbase + t * KT;
#pragma unroll
    for (int rep = 0; rep < 2; ++rep) {
        int c = tid + rep * 256;
        int row = c >> 2, seg = c & 3;
        CPA16(Bd + (uint32_t)(row * ROW_B + seg * 16),
              g_Zth + (size_t)row * NROWS + k0 + seg * 8);
    }
}

__global__ __launch_bounds__(256, 2) void gemm_kernel(const float* __restrict__ A) {
    extern __shared__ __align__(16) char sm[];
    uint32_t Au = smem_u32(sm);
    uint32_t Bu = Au + RING * TILE_B;

    int tid = threadIdx.x, wid = tid >> 5, lane = tid & 31;
    int m0 = blockIdx.x * 128;
    int kbase = blockIdx.y * KC;
    int mw = (wid >> 2) * 64, nw = (wid & 3) * 32;
    int r = lane >> 2, q = lane & 3;

    // ldmatrix per-lane address offsets (proven R9 mapping, ROW_B rows)
    int mi1 = (lane >> 3) & 1, mi2 = lane >> 4, rr = lane & 7;
    uint32_t aoff = (uint32_t)((mw + mi1 * 8 + rr) * ROW_B + mi2 * 16);
    uint32_t boff = (uint32_t)((nw + mi2 * 8 + rr) * ROW_B + mi1 * 16);

    float acc[4][4][4];
#pragma unroll
    for (int i = 0; i < 4; ++i)
#pragma unroll
        for (int j = 0; j < 4; ++j)
#pragma unroll
            for (int v = 0; v < 4; ++v) acc[i][j][v] = 0.f;

    float4 R[4];

    // prologue: B tiles 0..RING-2 in flight; A0 staged, A1 in regs
    ldgA(A, m0, kbase, 0, tid, R);
#pragma unroll
    for (int s = 0; s < RING - 1; ++s) {
        cpaB(Bu + s * TILE_B, kbase, s, tid);
        CPA_COMMIT();
    }
    cvtSTS(Au, tid, R);                  // A0 -> slot 0
    ldgA(A, m0, kbase, 1, tid, R);       // A1 in regs
    CPA_WAIT(RING - 2);                  // B0 arrived
    __syncthreads();

    uint32_t fa[4][4], fb[2][4];

    for (int t = 0; t < NKT; ++t) {
        if (t + RING - 1 < NKT)
            cpaB(Bu + ((t + RING - 1) % RING) * TILE_B, kbase, t + RING - 1, tid);
        CPA_COMMIT();
        if (t + 1 < NKT) cvtSTS(Au + ((t + 1) % RING) * TILE_B, tid, R);
        if (t + 2 < NKT) ldgA(A, m0, kbase, t + 2, tid, R);

        uint32_t At = Au + (t % RING) * TILE_B;
        uint32_t Bt = Bu + (t % RING) * TILE_B;

#pragma unroll
        for (int ks = 0; ks < 2; ++ks) {
            uint32_t ko = (uint32_t)(ks * 32);
#pragma unroll
            for (int i = 0; i < 4; ++i)
                ldsm_x4(fa[i], At + aoff + ko + (uint32_t)(i * 16 * ROW_B));
            ldsm_x4(fb[0], Bt + boff + ko);
            ldsm_x4(fb[1], Bt + boff + ko + (uint32_t)(16 * ROW_B));
#pragma unroll
            for (int i = 0; i < 4; ++i) {
                mma_f16(acc[i][0], fa[i], fb[0][0], fb[0][1]);
                mma_f16(acc[i][1], fa[i], fb[0][2], fb[0][3]);
                mma_f16(acc[i][2], fa[i], fb[1][0], fb[1][1]);
                mma_f16(acc[i][3], fa[i], fb[1][2], fb[1][3]);
            }
        }

        CPA_WAIT(RING - 2);  // B(t+1) arrived
        __syncthreads();     // also orders A(t+1) STS before its use
    }

    // write K-split partials
    float* P = g_part + (size_t)blockIdx.y * NROWS * ODIM;
#pragma unroll
    for (int i = 0; i < 4; ++i) {
        int row0 = m0 + mw + i * 16 + r;
#pragma unroll
        for (int j = 0; j < 4; ++j) {
            int col = nw + j * 8 + 2 * q;
            *reinterpret_cast<float2*>(&P[(size_t)row0 * ODIM + col]) =
                make_float2(acc[i][j][0], acc[i][j][1]);
            *reinterpret_cast<float2*>(&P[(size_t)(row0 + 8) * ODIM + col]) =
                make_float2(acc[i][j][2], acc[i][j][3]);
        }
    }
}

// ---------------------------------------------------------------------------
// Kernel 4: out = relu(d_m * sum_s p_s + b_n). grid 1024.
// ---------------------------------------------------------------------------
__global__ __launch_bounds__(256) void combine_kernel(const float* __restrict__ bias,
                                                      float* __restrict__ out) {
    const float4* P = reinterpret_cast<const float4*>(g_part);
    const size_t QT = (size_t)NROWS * ODIM / 4;
    float4* O = reinterpret_cast<float4*>(out);
    int i = blockIdx.x * 256 + threadIdx.x;
    float4 p0 = P[i];
    float4 p1 = P[i + QT];
    float4 p2 = P[i + 2 * QT];
    float4 p3 = P[i + 3 * QT];
    float sx = (p0.x + p1.x) + (p2.x + p3.x);
    float sy = (p0.y + p1.y) + (p2.y + p3.y);
    float sz = (p0.z + p1.z) + (p2.z + p3.z);
    float sw = (p0.w + p1.w) + (p2.w + p3.w);
    int m = i >> 5;
    int c = (i & 31) * 4;
    float4 bb = *reinterpret_cast<const float4*>(bias + c);
    float dv = g_d[m];
    float4 o;
    o.x = fmaxf(fmaf(dv, sx, bb.x), 0.f);
    o.y = fmaxf(fmaf(dv, sy, bb.y), 0.f);
    o.z = fmaxf(fmaf(dv, sz, bb.z), 0.f);
    o.w = fmaxf(fmaf(dv, sw, bb.w), 0.f);
    O[i] = o;
}

// ---------------------------------------------------------------------------
extern "C" void kernel_launch(void* const* d_in, const int* in_sizes, int n_in,
                              void* d_out, int out_size) {
    const float* A = (const float*)d_in[0];
    const float* X = (const float*)d_in[1];
    const float* W = (const float*)d_in[2];
    const float* b = (const float*)d_in[3];
    float* out = (float*)d_out;
    (void)in_sizes; (void)n_in; (void)out_size;

    rowsum_kernel<<<NROWS, 256>>>(A);
    dim3 g2(NROWS / 16, 2);
    xw_kernel<<<g2, 256>>>(X, W);
    cudaFuncSetAttribute(gemm_kernel,
                         cudaFuncAttributeMaxDynamicSharedMemorySize, DYN_SMEM);
    dim3 g3(NROWS / 128, KSPLIT);
    gemm_kernel<<<g3, 256, DYN_SMEM>>>(A);
    combine_kernel<<<NROWS * ODIM / 4 / 256, 256>>>(b, out);
}